// round 3
// baseline (speedup 1.0000x reference)
#include <cuda_runtime.h>
#include <math.h>

// Problem constants (fixed by the dataset): H_IN=W_IN=1024, STRIDE=4 -> 256x256 grid,
// B=16, C_sal=32, NUM_CLS=2, N targets=256.
#define FH 256
#define FW 256
#define HWC 65536          // FH*FW
#define BDIM 16
#define TOTAL (BDIM*HWC)   // 1,048,576 cells
#define EPSF 1e-7f

// Scratch (no allocations allowed): winner-priority map + gaussian mask + accumulators.
__device__ int          g_win[TOTAL];     // 4 MB
__device__ unsigned int g_mask[TOTAL];    // 4 MB (float bits, all values >= 0)
__device__ double       g_acc[8];         // [0]=attn_sse [1]=npos [2]=conf [3]=ciou [4]=cls

// ---------------------------------------------------------------------------
__global__ void k_clear() {
    int stride = gridDim.x * blockDim.x;
    for (int i = blockIdx.x * blockDim.x + threadIdx.x; i < TOTAL; i += stride) {
        g_win[i]  = -1;
        g_mask[i] = 0u;
    }
    if (blockIdx.x == 0 && threadIdx.x < 8) g_acc[threadIdx.x] = 0.0;
}

// ---------------------------------------------------------------------------
// One block per target: assignment candidates (10 atomicMax) + truncated
// gaussian scatter (33x33 window, atomicMax on float bits).
__global__ void k_scatter(const float* __restrict__ tg) {
    int n = blockIdx.x;
    float cx = tg[n * 6 + 1], cy = tg[n * 6 + 2];
    float w  = tg[n * 6 + 3], h  = tg[n * 6 + 4];
    int b = (int)tg[n * 6 + 0];
    int base = b * HWC;
    int t = threadIdx.x;

    if (t < 10) {
        int gi = (int)(cx * (float)FW);
        int gj = (int)(cy * (float)FH);
        int cell;
        bool valid;
        if (t < 9) {
            // dx = [-1,-1,-1,0,0,0,1,1,1], dy = [-1,0,1,...]
            int nx = gi + (t / 3) - 1;
            int ny = gj + (t % 3) - 1;
            valid = (nx >= 0 && nx < FW && ny >= 0 && ny < FH);
            if (valid) {
                float ccx = ((float)nx + 0.5f) / (float)FW;
                float ccy = ((float)ny + 0.5f) / (float)FH;
                valid = (fabsf(ccx - cx) <= w * 0.5f) && (fabsf(ccy - cy) <= h * 0.5f);
            }
            cell = ny * FW + nx;
        } else {
            cell = min(gj, FH - 1) * FW + min(gi, FW - 1);
            valid = true;
        }
        if (valid) atomicMax(&g_win[base + cell], n * 10 + t);
    }

    // Gaussian scatter: exp(-d2/4.5) < 2e-25 beyond |d|>=16, negligible vs 1e-3 tol.
    float tx = cx * (float)FW, ty = cy * (float)FH;
    int x0 = max(0, (int)tx - 16), x1 = min(FW - 1, (int)tx + 16);
    int y0 = max(0, (int)ty - 16), y1 = min(FH - 1, (int)ty + 16);
    int nx = x1 - x0 + 1;
    int tot = nx * (y1 - y0 + 1);
    for (int k = t; k < tot; k += blockDim.x) {
        int x = x0 + k % nx;
        int y = y0 + k / nx;
        float dx = (float)x - tx, dy = (float)y - ty;
        float g = expf(-(dx * dx + dy * dy) / 4.5f);   // 2*SIGMA^2 = 4.5
        // non-negative floats: unsigned-int compare == float compare
        atomicMax(&g_mask[base + y * FW + x], __float_as_uint(g));
    }
}

// ---------------------------------------------------------------------------
__device__ __forceinline__ float sigm(float x)  { return 1.0f / (1.0f + expf(-x)); }
__device__ __forceinline__ float softp(float x) { return fmaxf(x, 0.0f) + log1pf(expf(-fabsf(x))); }

__global__ void __launch_bounds__(256)
k_main(const float* __restrict__ raw, const float* __restrict__ sal,
       const float* __restrict__ tg) {
    int t4   = blockIdx.x * blockDim.x + threadIdx.x;   // one thread = 4 cells
    int idx0 = t4 * 4;                                   // global cell index (b*HW + i)

    // raw_grid: 4 cells * 7 ch = 28 floats = 7 aligned float4
    union { float4 v[7]; float f[28]; } u;
    const float4* rp = (const float4*)(raw + (size_t)idx0 * 7);
#pragma unroll
    for (int k = 0; k < 7; k++) u.v[k] = rp[k];

    int4  winv = *(const int4*)(g_win + idx0);
    uint4 mv   = *(const uint4*)(g_mask + idx0);

    int b = idx0 >> 16;            // / HWC
    int i = idx0 & (HWC - 1);
    const float* sb = sal + (size_t)b * 32 * HWC + i;
    float4 ss = make_float4(0.f, 0.f, 0.f, 0.f);
#pragma unroll
    for (int c = 0; c < 32; c++) {
        float4 v = *(const float4*)(sb + (size_t)c * HWC);
        ss.x += v.x; ss.y += v.y; ss.z += v.z; ss.w += v.w;
    }

    float attn = 0.f, conf_s = 0.f, ciou_s = 0.f, cls_s = 0.f;
    int npos = 0;
    int   wins[4]  = {winv.x, winv.y, winv.z, winv.w};
    float masks[4] = {__uint_as_float(mv.x), __uint_as_float(mv.y),
                      __uint_as_float(mv.z), __uint_as_float(mv.w)};
    float sals[4]  = {ss.x, ss.y, ss.z, ss.w};

#pragma unroll
    for (int j = 0; j < 4; j++) {
        float sm = sals[j] * (1.0f / 32.0f);
        float dm = sm - masks[j];
        attn += dm * dm;

        float z0 = u.f[j * 7 + 0], z1 = u.f[j * 7 + 1], z2 = u.f[j * 7 + 2];
        float z3 = u.f[j * 7 + 3], z4 = u.f[j * 7 + 4];
        float z5 = u.f[j * 7 + 5], z6 = u.f[j * 7 + 6];

        int cell = i + j;
        int gx = cell & (FW - 1);
        int gy = cell >> 8;
        int win = wins[j];
        bool obj = (win >= 0);

        // focal conf loss, all cells
        float conf = sigm(z4);
        float bce  = obj ? softp(-z4) : softp(z4);
        float pt   = obj ? conf : 1.0f - conf;
        float at   = obj ? 0.25f : 0.75f;
        float om   = 1.0f - pt;
        conf_s += at * om * om * bce;

        if (obj) {
            npos++;
            int n = win / 10;
            float tcx = tg[n * 6 + 1], tcy = tg[n * 6 + 2];
            float tw  = tg[n * 6 + 3], th  = tg[n * 6 + 4];
            int   cls = (int)tg[n * 6 + 5];

            float pcx = (sigm(z0) + (float)gx) / (float)FW;
            float pcy = (sigm(z1) + (float)gy) / (float)FH;
            float pw  = expf(fminf(fmaxf(z2, -4.0f), 4.0f)) / (float)FW;
            float ph  = expf(fminf(fmaxf(z3, -4.0f), 4.0f)) / (float)FH;

            // CIoU
            float px1 = pcx - pw * 0.5f, px2 = pcx + pw * 0.5f;
            float py1 = pcy - ph * 0.5f, py2 = pcy + ph * 0.5f;
            float tx1 = tcx - tw * 0.5f, tx2 = tcx + tw * 0.5f;
            float ty1 = tcy - th * 0.5f, ty2 = tcy + th * 0.5f;
            float iw = fmaxf(fminf(px2, tx2) - fmaxf(px1, tx1), 0.0f);
            float ih = fmaxf(fminf(py2, ty2) - fmaxf(py1, ty1), 0.0f);
            float inter = iw * ih;
            float uni   = pw * ph + tw * th - inter;
            float iou   = inter / (uni + EPSF);
            float cw  = fmaxf(px2, tx2) - fminf(px1, tx1);
            float chh = fmaxf(py2, ty2) - fminf(py1, ty1);
            float c2  = cw * cw + chh * chh + EPSF;
            float dd  = (pcx - tcx) * (pcx - tcx) + (pcy - tcy) * (pcy - tcy);
            float dv  = atanf(tw / (th + EPSF)) - atanf(pw / (ph + EPSF));
            float v   = 0.4052847345693511f * dv * dv;   // 4/pi^2
            float alpha = v / (1.0f - iou + v + EPSF);
            ciou_s += 1.0f - iou + dd / c2 + alpha * v;

            // 2-class cross entropy (log_softmax with max shift)
            float m   = fmaxf(z5, z6);
            float lse = m + logf(expf(z5 - m) + expf(z6 - m));
            float zc  = (cls == 0) ? z5 : z6;
            cls_s += lse - zc;
        }
    }

    // block reduction: warp shuffle -> shared -> double atomicAdd
    float vals[5] = {attn, (float)npos, conf_s, ciou_s, cls_s};
#pragma unroll
    for (int q = 0; q < 5; q++) {
        float v = vals[q];
#pragma unroll
        for (int o = 16; o > 0; o >>= 1) v += __shfl_xor_sync(0xffffffffu, v, o);
        vals[q] = v;
    }
    __shared__ float sh[5][8];
    int lane = threadIdx.x & 31, wid = threadIdx.x >> 5;
    if (lane == 0) {
#pragma unroll
        for (int q = 0; q < 5; q++) sh[q][wid] = vals[q];
    }
    __syncthreads();
    if (threadIdx.x == 0) {
#pragma unroll
        for (int q = 0; q < 5; q++) {
            double s = 0.0;
#pragma unroll
            for (int ww = 0; ww < 8; ww++) s += (double)sh[q][ww];
            atomicAdd(&g_acc[q], s);
        }
    }
}

// ---------------------------------------------------------------------------
__global__ void k_final(float* __restrict__ out) {
    double norm = fmax(g_acc[1], 1.0);
    double loss = 2.0 * g_acc[3] / norm        // L_CIOU
                + 1.0 * g_acc[2] / norm        // L_CONF
                + 1.0 * g_acc[4] / norm        // L_CLS
                + 5.0 * g_acc[0] / (double)TOTAL; // L_ATTN (mean over B*H*W)
    out[0] = (float)loss;
}

// ---------------------------------------------------------------------------
extern "C" void kernel_launch(void* const* d_in, const int* in_sizes, int n_in,
                              void* d_out, int out_size) {
    const float* raw = (const float*)d_in[0];   // (16, 65536, 7)
    const float* sal = (const float*)d_in[1];   // (16, 32, 256, 256)
    const float* tg  = (const float*)d_in[2];   // (256, 6)
    int N = in_sizes[2] / 6;

    k_clear<<<512, 256>>>();
    k_scatter<<<N, 128>>>(tg);
    k_main<<<TOTAL / 4 / 256, 256>>>(raw, sal, tg);
    k_final<<<1, 1>>>((float*)d_out);
}